// round 2
// baseline (speedup 1.0000x reference)
#include <cuda_runtime.h>

// Problem constants (fixed by the reference)
#define BN   4096
#define LEN  60
#define TS   60
#define HD   256
#define ID   6
#define OD   6
#define GD   1024      // 4*H
#define ROWS 16        // batch rows per CTA
#define NTH  256
#define KD   264       // decoder input K (262) padded to 264 for 16B alignment
#define NCTA (BN / ROWS)

typedef unsigned long long u64;

// ---------------- device scratch (allocation-free: static __device__ globals) ----------------
__device__ float g_WihT_e[ID * GD];
__device__ float g_WhhT_e[HD * GD];
__device__ float g_be[GD];
__device__ float g_WihT_d[KD * GD];   // rows 262..263 zero
__device__ float g_WhhT_d[HD * GD];
__device__ float g_bd[GD];
__device__ float g_l1T[HD * HD];
__device__ float g_l2T[HD * OD];
__device__ float g_attnW[LEN * KD];   // padded row stride 264
__device__ float g_enc[(size_t)BN * LEN * HD];   // encoder outputs [B][L][H]

// ---------------- packed fp32x2 helpers (FFMA2: 2x fp32 throughput on sm_103a) ----------------
__device__ __forceinline__ u64 pack2(float v) {
    u64 r; asm("mov.b64 %0, {%1, %1};" : "=l"(r) : "f"(v)); return r;
}
__device__ __forceinline__ u64 fma2(u64 a, u64 b, u64 c) {
    u64 d; asm("fma.rn.f32x2 %0, %1, %2, %3;" : "=l"(d) : "l"(a), "l"(b), "l"(c)); return d;
}
__device__ __forceinline__ float2 unpk(u64 v) {
    float2 f; asm("mov.b64 {%0, %1}, %2;" : "=f"(f.x), "=f"(f.y) : "l"(v)); return f;
}
__device__ __forceinline__ float sigmf(float x) { return 1.0f / (1.0f + __expf(-x)); }

// Accumulate acc[4 rows][8 u64 (=16 cols)] += A_smem[row][k] * W[k][j0..j0+16) over k in [0,K)
// A rows broadcast from smem (all lanes in a warp share rg -> broadcast), W streamed LDG.128.
__device__ __forceinline__ void gemm_part(u64 acc[4][8],
                                          const float* __restrict__ Asm, int lda, int K,
                                          const float* __restrict__ W, int rg, int j0) {
    for (int k = 0; k < K; k += 4) {
        float4 av[4];
#pragma unroll
        for (int i = 0; i < 4; i++)
            av[i] = *(const float4*)&Asm[(rg * 4 + i) * lda + k];
#pragma unroll
        for (int kk = 0; kk < 4; kk++) {
            const ulonglong2* wp = (const ulonglong2*)&W[(k + kk) * GD + j0];
            ulonglong2 w0 = wp[0], w1 = wp[1], w2 = wp[2], w3 = wp[3];
#pragma unroll
            for (int i = 0; i < 4; i++) {
                u64 ab = pack2(((const float*)&av[i])[kk]);
                acc[i][0] = fma2(ab, w0.x, acc[i][0]);
                acc[i][1] = fma2(ab, w0.y, acc[i][1]);
                acc[i][2] = fma2(ab, w1.x, acc[i][2]);
                acc[i][3] = fma2(ab, w1.y, acc[i][3]);
                acc[i][4] = fma2(ab, w2.x, acc[i][4]);
                acc[i][5] = fma2(ab, w2.y, acc[i][5]);
                acc[i][6] = fma2(ab, w3.x, acc[i][6]);
                acc[i][7] = fma2(ab, w3.y, acc[i][7]);
            }
        }
    }
}

// ---------------- prep: transpose weights, fold biases, pad ----------------
__global__ void prep_kernel(const float* __restrict__ eWih, const float* __restrict__ eWhh,
                            const float* __restrict__ ebih, const float* __restrict__ ebhh,
                            const float* __restrict__ aW,
                            const float* __restrict__ dWih, const float* __restrict__ dWhh,
                            const float* __restrict__ dbih, const float* __restrict__ dbhh,
                            const float* __restrict__ l1W, const float* __restrict__ l2W) {
    int tid = blockIdx.x * blockDim.x + threadIdx.x;
    int stride = gridDim.x * blockDim.x;
    for (int i = tid; i < ID * GD; i += stride) { int k = i / GD, j = i % GD; g_WihT_e[i] = eWih[j * ID + k]; }
    for (int i = tid; i < HD * GD; i += stride) { int k = i / GD, j = i % GD; g_WhhT_e[i] = eWhh[j * HD + k]; }
    for (int i = tid; i < GD; i += stride) g_be[i] = ebih[i] + ebhh[i];
    for (int i = tid; i < KD * GD; i += stride) { int k = i / GD, j = i % GD; g_WihT_d[i] = (k < 262) ? dWih[j * 262 + k] : 0.0f; }
    for (int i = tid; i < HD * GD; i += stride) { int k = i / GD, j = i % GD; g_WhhT_d[i] = dWhh[j * HD + k]; }
    for (int i = tid; i < GD; i += stride) g_bd[i] = dbih[i] + dbhh[i];
    for (int i = tid; i < HD * HD; i += stride) { int k = i / HD, u = i % HD; g_l1T[i] = l1W[u * HD + k]; }
    for (int i = tid; i < HD * OD; i += stride) { int k = i / OD, o = i % OD; g_l2T[i] = l2W[o * HD + k]; }
    for (int i = tid; i < LEN * KD; i += stride) { int l = i / KD, k = i % KD; g_attnW[i] = (k < 262) ? aW[l * 262 + k] : 0.0f; }
}

// ---------------- main: one CTA owns 16 batch rows end-to-end ----------------
__global__ void __launch_bounds__(NTH, 1) seq_kernel(const float* __restrict__ x,
                                                     const float* __restrict__ attn_b,
                                                     const float* __restrict__ l1b,
                                                     const float* __restrict__ l2b,
                                                     float* __restrict__ out) {
    extern __shared__ float sm[];
    float* h_s   = sm;                    // ROWS*HD
    float* c_s   = h_s + ROWS * HD;       // ROWS*HD
    float* g_s   = c_s + ROWS * HD;       // ROWS*GD (gates; reused for l1 output z)
    float* inp_s = g_s + ROWS * GD;       // ROWS*KD  ([tok(6) | ctx(256) | pad(2)])
    float* s_s   = inp_s + ROWS * KD;     // ROWS*64  (attn scores -> weights)
    float* x_s   = s_s + ROWS * 64;       // ROWS*8

    const int t  = threadIdx.x;
    const int r0 = blockIdx.x * ROWS;
    const int rg = t >> 6;                // 4 row-groups of 4 rows
    const int j0 = (t & 63) << 4;         // 16 contiguous gate columns per thread

    for (int i = t; i < ROWS * HD; i += NTH) { h_s[i] = 0.0f; c_s[i] = 0.0f; }
    __syncthreads();

    // ================= encoder =================
    for (int step = 0; step < LEN; step++) {
        if (t < ROWS * ID) {
            int r = t / ID, k = t - r * ID;
            x_s[r * 8 + k] = x[(size_t)(r0 + r) * (LEN * ID) + step * ID + k];
        }
        __syncthreads();

        u64 acc[4][8];
        {
            const ulonglong2* bp = (const ulonglong2*)&g_be[j0];
            ulonglong2 b0 = bp[0], b1 = bp[1], b2 = bp[2], b3 = bp[3];
#pragma unroll
            for (int i = 0; i < 4; i++) {
                acc[i][0] = b0.x; acc[i][1] = b0.y; acc[i][2] = b1.x; acc[i][3] = b1.y;
                acc[i][4] = b2.x; acc[i][5] = b2.y; acc[i][6] = b3.x; acc[i][7] = b3.y;
            }
        }
        // x @ WihT (K=6)
#pragma unroll
        for (int k = 0; k < ID; k++) {
            const ulonglong2* wp = (const ulonglong2*)&g_WihT_e[k * GD + j0];
            ulonglong2 w0 = wp[0], w1 = wp[1], w2 = wp[2], w3 = wp[3];
#pragma unroll
            for (int i = 0; i < 4; i++) {
                u64 ab = pack2(x_s[(rg * 4 + i) * 8 + k]);
                acc[i][0] = fma2(ab, w0.x, acc[i][0]); acc[i][1] = fma2(ab, w0.y, acc[i][1]);
                acc[i][2] = fma2(ab, w1.x, acc[i][2]); acc[i][3] = fma2(ab, w1.y, acc[i][3]);
                acc[i][4] = fma2(ab, w2.x, acc[i][4]); acc[i][5] = fma2(ab, w2.y, acc[i][5]);
                acc[i][6] = fma2(ab, w3.x, acc[i][6]); acc[i][7] = fma2(ab, w3.y, acc[i][7]);
            }
        }
        // h @ WhhT (K=256)
        gemm_part(acc, h_s, HD, HD, g_WhhT_e, rg, j0);
#pragma unroll
        for (int i = 0; i < 4; i++) {
            ulonglong2* gp = (ulonglong2*)&g_s[(rg * 4 + i) * GD + j0];
            ulonglong2 s0; s0.x = acc[i][0]; s0.y = acc[i][1]; gp[0] = s0;
            ulonglong2 s1; s1.x = acc[i][2]; s1.y = acc[i][3]; gp[1] = s1;
            ulonglong2 s2; s2.x = acc[i][4]; s2.y = acc[i][5]; gp[2] = s2;
            ulonglong2 s3; s3.x = acc[i][6]; s3.y = acc[i][7]; gp[3] = s3;
        }
        __syncthreads();

        // cell update + write enc_out (u interleaved: conflict-free LDS + coalesced STG)
        {
            int r = t >> 4, ul = t & 15;
            float* gr = &g_s[r * GD];
            float* hr = &h_s[r * HD];
            float* cr = &c_s[r * HD];
            float* er = &g_enc[(size_t)(r0 + r) * (LEN * HD) + step * HD];
#pragma unroll
            for (int z = 0; z < 16; z++) {
                int u = ul + z * 16;
                float gi = gr[u], gf = gr[HD + u], gg = gr[2 * HD + u], go = gr[3 * HD + u];
                float cc = sigmf(gf) * cr[u] + sigmf(gi) * tanhf(gg);
                float hh = sigmf(go) * tanhf(cc);
                cr[u] = cc; hr[u] = hh; er[u] = hh;
            }
        }
        __syncthreads();
    }

    // ================= decoder init: c=0, tok=GO =================
    for (int i = t; i < ROWS * HD; i += NTH) c_s[i] = 0.0f;
    if (t < ROWS) {
#pragma unroll
        for (int k = 0; k < OD; k++) inp_s[t * KD + k] = (k == 4) ? 1.0f : 0.0f;
        inp_s[t * KD + 262] = 0.0f; inp_s[t * KD + 263] = 0.0f;
    }
    __syncthreads();

    // ================= decoder =================
    for (int step = 0; step < TS; step++) {
        // attention scores: s[r][l] = [h, tok] . attn_W[l] + b[l]
        for (int idx = t; idx < ROWS * LEN; idx += NTH) {
            int r = idx / LEN, l = idx - r * LEN;
            const float* wr = &g_attnW[l * KD];
            const float4* wp4 = (const float4*)wr;
            const float4* hp4 = (const float4*)&h_s[r * HD];
            float4 a4 = make_float4(0.0f, 0.0f, 0.0f, 0.0f);
#pragma unroll 8
            for (int k = 0; k < HD / 4; k++) {
                float4 hv = hp4[k], wv = wp4[k];
                a4.x += hv.x * wv.x; a4.y += hv.y * wv.y;
                a4.z += hv.z * wv.z; a4.w += hv.w * wv.w;
            }
            float s = attn_b[l] + a4.x + a4.y + a4.z + a4.w;
#pragma unroll
            for (int k = 0; k < OD; k++) s += inp_s[r * KD + k] * wr[HD + k];
            s_s[r * 64 + l] = s;
        }
        __syncthreads();
        // softmax (one thread per row; tiny)
        if (t < ROWS) {
            float* sp = &s_s[t * 64];
            float m = -1e30f;
            for (int l = 0; l < LEN; l++) m = fmaxf(m, sp[l]);
            float ssum = 0.0f;
            for (int l = 0; l < LEN; l++) { float e = __expf(sp[l] - m); sp[l] = e; ssum += e; }
            float inv = 1.0f / ssum;
            for (int l = 0; l < LEN; l++) sp[l] *= inv;
        }
        __syncthreads();
        // ctx[r][h] = sum_l aw[r][l] * enc_out[r][l][h]  -> inp_s[r][6+h]
        {
            int r = t >> 4, h0 = (t & 15) * 16;
            u64 a8[8];
#pragma unroll
            for (int z = 0; z < 8; z++) a8[z] = 0ULL;
            const float* ep = &g_enc[(size_t)(r0 + r) * (LEN * HD) + h0];
            const float* ap = &s_s[r * 64];
            for (int l = 0; l < LEN; l++) {
                u64 ab = pack2(ap[l]);
                const ulonglong2* e2 = (const ulonglong2*)(ep + (size_t)l * HD);
                ulonglong2 e0 = e2[0], e1 = e2[1], e2v = e2[2], e3 = e2[3];
                a8[0] = fma2(ab, e0.x, a8[0]);  a8[1] = fma2(ab, e0.y, a8[1]);
                a8[2] = fma2(ab, e1.x, a8[2]);  a8[3] = fma2(ab, e1.y, a8[3]);
                a8[4] = fma2(ab, e2v.x, a8[4]); a8[5] = fma2(ab, e2v.y, a8[5]);
                a8[6] = fma2(ab, e3.x, a8[6]);  a8[7] = fma2(ab, e3.y, a8[7]);
            }
            float* dst = &inp_s[r * KD + OD + h0];
#pragma unroll
            for (int z = 0; z < 8; z++) { float2 f = unpk(a8[z]); dst[2 * z] = f.x; dst[2 * z + 1] = f.y; }
        }
        __syncthreads();

        // decoder LSTM gates: g = inp @ dec_WihT (K=264, zero-padded) + h @ dec_WhhT + b
        u64 acc[4][8];
        {
            const ulonglong2* bp = (const ulonglong2*)&g_bd[j0];
            ulonglong2 b0 = bp[0], b1 = bp[1], b2 = bp[2], b3 = bp[3];
#pragma unroll
            for (int i = 0; i < 4; i++) {
                acc[i][0] = b0.x; acc[i][1] = b0.y; acc[i][2] = b1.x; acc[i][3] = b1.y;
                acc[i][4] = b2.x; acc[i][5] = b2.y; acc[i][6] = b3.x; acc[i][7] = b3.y;
            }
        }
        gemm_part(acc, inp_s, KD, KD, g_WihT_d, rg, j0);
        gemm_part(acc, h_s, HD, HD, g_WhhT_d, rg, j0);
#pragma unroll
        for (int i = 0; i < 4; i++) {
            ulonglong2* gp = (ulonglong2*)&g_s[(rg * 4 + i) * GD + j0];
            ulonglong2 s0; s0.x = acc[i][0]; s0.y = acc[i][1]; gp[0] = s0;
            ulonglong2 s1; s1.x = acc[i][2]; s1.y = acc[i][3]; gp[1] = s1;
            ulonglong2 s2; s2.x = acc[i][4]; s2.y = acc[i][5]; gp[2] = s2;
            ulonglong2 s3; s3.x = acc[i][6]; s3.y = acc[i][7]; gp[3] = s3;
        }
        __syncthreads();

        // cell update
        {
            int r = t >> 4, ul = t & 15;
            float* gr = &g_s[r * GD];
            float* hr = &h_s[r * HD];
            float* cr = &c_s[r * HD];
#pragma unroll
            for (int z = 0; z < 16; z++) {
                int u = ul + z * 16;
                float gi = gr[u], gf = gr[HD + u], gg = gr[2 * HD + u], go = gr[3 * HD + u];
                float cc = sigmf(gf) * cr[u] + sigmf(gi) * tanhf(gg);
                float hh = sigmf(go) * tanhf(cc);
                cr[u] = cc; hr[u] = hh;
            }
        }
        __syncthreads();

        // l1: z = relu(h @ l1T + b1)  -> store into g_s[r][u] (u < 256)
        {
            int u0 = (t & 63) * 4;
            u64 az[4][2];
            ulonglong2 lb = *(const ulonglong2*)&l1b[u0];
#pragma unroll
            for (int i = 0; i < 4; i++) { az[i][0] = lb.x; az[i][1] = lb.y; }
            for (int k = 0; k < HD; k += 4) {
                float4 hv[4];
#pragma unroll
                for (int i = 0; i < 4; i++) hv[i] = *(const float4*)&h_s[(rg * 4 + i) * HD + k];
#pragma unroll
                for (int kk = 0; kk < 4; kk++) {
                    ulonglong2 w = *(const ulonglong2*)&g_l1T[(k + kk) * HD + u0];
#pragma unroll
                    for (int i = 0; i < 4; i++) {
                        u64 ab = pack2(((const float*)&hv[i])[kk]);
                        az[i][0] = fma2(ab, w.x, az[i][0]);
                        az[i][1] = fma2(ab, w.y, az[i][1]);
                    }
                }
            }
#pragma unroll
            for (int i = 0; i < 4; i++) {
                float2 f0 = unpk(az[i][0]), f1 = unpk(az[i][1]);
                float* zr = &g_s[(rg * 4 + i) * GD + u0];
                zr[0] = fmaxf(f0.x, 0.0f); zr[1] = fmaxf(f0.y, 0.0f);
                zr[2] = fmaxf(f1.x, 0.0f); zr[3] = fmaxf(f1.y, 0.0f);
            }
        }
        __syncthreads();

        // l2 + output + token feedback
        if (t < ROWS * OD) {
            int r = t / OD, o = t - r * OD;
            float s = l2b[o];
            const float* zr = &g_s[r * GD];
            for (int k = 0; k < HD; k++) s += zr[k] * g_l2T[k * OD + o];
            out[(size_t)(r0 + r) * (TS * OD) + step * OD + o] = s;
            inp_s[r * KD + o] = s;
        }
        __syncthreads();
    }
}

extern "C" void kernel_launch(void* const* d_in, const int* in_sizes, int n_in,
                              void* d_out, int out_size) {
    const float* x    = (const float*)d_in[0];
    // d_in[1] = target (unused; only its length T=60 matters, which is compile-time)
    const float* eWih = (const float*)d_in[2];
    const float* eWhh = (const float*)d_in[3];
    const float* ebih = (const float*)d_in[4];
    const float* ebhh = (const float*)d_in[5];
    const float* aW   = (const float*)d_in[6];
    const float* ab   = (const float*)d_in[7];
    const float* dWih = (const float*)d_in[8];
    const float* dWhh = (const float*)d_in[9];
    const float* dbih = (const float*)d_in[10];
    const float* dbhh = (const float*)d_in[11];
    const float* l1W  = (const float*)d_in[12];
    const float* l1b  = (const float*)d_in[13];
    const float* l2W  = (const float*)d_in[14];
    const float* l2b  = (const float*)d_in[15];
    float* out = (float*)d_out;

    prep_kernel<<<256, 256>>>(eWih, eWhh, ebih, ebhh, aW, dWih, dWhh, dbih, dbhh, l1W, l2W);

    const int smem_bytes = (ROWS * HD * 2 + ROWS * GD + ROWS * KD + ROWS * 64 + ROWS * 8) * (int)sizeof(float);
    cudaFuncSetAttribute(seq_kernel, cudaFuncAttributeMaxDynamicSharedMemorySize, smem_bytes);
    seq_kernel<<<NCTA, NTH, smem_bytes>>>(x, ab, l1b, l2b, out);
}

// round 3
// speedup vs baseline: 1.2276x; 1.2276x over previous
#include <cuda_runtime.h>

#define BN   4096
#define LEN  60
#define TS   60
#define HD   256
#define ID   6
#define OD   6
#define GD   1024
#define ROWS 32
#define NTH  256
#define KDD  264     // decoder input K (262) padded
#define NCTA (BN / ROWS)
#define AST  34      // u64 stride per k-row in dup'd activation buffers (pad: bank spread)

typedef unsigned long long u64;

// ---------------- device scratch (allocation-free) ----------------
// Gate-interleaved weights: Wg[k][u*4+g] = W_orig[g*256+u][k]  (g: 0=i,1=f,2=g,3=o)
__device__ float g_Wg_e_ih[ID * GD];
__device__ float g_Wg_e_hh[HD * GD];
__device__ float g_bg_e[GD];
__device__ float g_Wg_d_ih[KDD * GD];   // k rows 262..263 zero
__device__ float g_Wg_d_hh[HD * GD];
__device__ float g_bg_d[GD];
__device__ float g_l1T[HD * HD];        // [k][u]
__device__ float g_l2T[HD * OD];        // [u][o]
__device__ float g_attnT[KDD * 64];     // [k][l], zero padded
__device__ float g_enc[(size_t)BN * LEN * HD];

// ---------------- packed fp32x2 helpers ----------------
__device__ __forceinline__ u64 pack2(float v) {
    u64 r; asm("mov.b64 %0, {%1, %1};" : "=l"(r) : "f"(v)); return r;
}
__device__ __forceinline__ u64 fma2(u64 a, u64 b, u64 c) {
    u64 d; asm("fma.rn.f32x2 %0, %1, %2, %3;" : "=l"(d) : "l"(a), "l"(b), "l"(c)); return d;
}
__device__ __forceinline__ float2 unpk(u64 v) {
    float2 f; asm("mov.b64 {%0, %1}, %2;" : "=f"(f.x), "=f"(f.y) : "l"(v)); return f;
}
__device__ __forceinline__ float lo32(u64 v) { return __uint_as_float((unsigned)v); }
__device__ __forceinline__ float sigmf(float x) { return 1.0f / (1.0f + __expf(-x)); }

// gate GEMM: thread t owns unit t (gate cols 4t..4t+3) for all 32 rows.
// Ad: dup'd activations [k][row] (u64, stride AST). Wg: [K][1024] gate-interleaved.
__device__ __forceinline__ void gemm_acc(u64 acc[ROWS][2], const u64* __restrict__ Ad,
                                         const float* __restrict__ Wg, int K, int t) {
    const char* Wp = (const char*)(Wg + 4 * t);
#pragma unroll 2
    for (int k = 0; k < K; k++) {
        ulonglong2 w = *(const ulonglong2*)(Wp + (size_t)k * 4096);
        const u64* ar = Ad + k * AST;
#pragma unroll
        for (int i = 0; i < ROWS; i++) {
            acc[i][0] = fma2(ar[i], w.x, acc[i][0]);
            acc[i][1] = fma2(ar[i], w.y, acc[i][1]);
        }
    }
}

// ---------------- prep: permute/transpose weights, fold biases ----------------
__global__ void prep_kernel(const float* __restrict__ eWih, const float* __restrict__ eWhh,
                            const float* __restrict__ ebih, const float* __restrict__ ebhh,
                            const float* __restrict__ aW,
                            const float* __restrict__ dWih, const float* __restrict__ dWhh,
                            const float* __restrict__ dbih, const float* __restrict__ dbhh,
                            const float* __restrict__ l1W, const float* __restrict__ l2W) {
    int tid = blockIdx.x * blockDim.x + threadIdx.x;
    int stride = gridDim.x * blockDim.x;
    for (int i = tid; i < ID * GD; i += stride) {
        int k = i / GD, cc = i % GD, u = cc >> 2, g = cc & 3;
        g_Wg_e_ih[i] = eWih[(g * HD + u) * ID + k];
    }
    for (int i = tid; i < HD * GD; i += stride) {
        int k = i / GD, cc = i % GD, u = cc >> 2, g = cc & 3;
        g_Wg_e_hh[i] = eWhh[(g * HD + u) * HD + k];
    }
    for (int i = tid; i < GD; i += stride) {
        int u = i >> 2, g = i & 3;
        g_bg_e[i] = ebih[g * HD + u] + ebhh[g * HD + u];
    }
    for (int i = tid; i < KDD * GD; i += stride) {
        int k = i / GD, cc = i % GD, u = cc >> 2, g = cc & 3;
        g_Wg_d_ih[i] = (k < 262) ? dWih[(g * HD + u) * 262 + k] : 0.0f;
    }
    for (int i = tid; i < HD * GD; i += stride) {
        int k = i / GD, cc = i % GD, u = cc >> 2, g = cc & 3;
        g_Wg_d_hh[i] = dWhh[(g * HD + u) * HD + k];
    }
    for (int i = tid; i < GD; i += stride) {
        int u = i >> 2, g = i & 3;
        g_bg_d[i] = dbih[g * HD + u] + dbhh[g * HD + u];
    }
    for (int i = tid; i < HD * HD; i += stride) { int k = i / HD, u = i % HD; g_l1T[i] = l1W[u * HD + k]; }
    for (int i = tid; i < HD * OD; i += stride) { int k = i / OD, o = i % OD; g_l2T[i] = l2W[o * HD + k]; }
    for (int i = tid; i < KDD * 64; i += stride) {
        int k = i / 64, l = i % 64;
        g_attnT[i] = (k < 262 && l < LEN) ? aW[l * 262 + k] : 0.0f;
    }
}

// ---------------- main: one CTA owns 32 batch rows end-to-end ----------------
__global__ void __launch_bounds__(NTH, 1) seq_kernel(const float* __restrict__ x,
                                                     const float* __restrict__ attn_b,
                                                     const float* __restrict__ l1b,
                                                     const float* __restrict__ l2b,
                                                     float* __restrict__ out) {
    extern __shared__ char smraw[];
    u64*   Ah  = (u64*)smraw;            // h, dup'd  [256][AST]
    u64*   Ain = Ah + HD * AST;          // dec input [264][AST]  (0-5 tok | 6-261 ctx | pad)
    u64*   Ax  = Ain + KDD * AST;        // enc x     [8][AST]
    float* s_s = (float*)(Ax + 8 * AST); // scores    [32][65]
    float* z_s = s_s + 32 * 65;          // l1 output [256][33]

    const int t  = threadIdx.x;
    const int r0 = blockIdx.x * ROWS;

    for (int i = t; i < HD * AST; i += NTH) Ah[i] = 0ULL;   // h0 = 0

    float c[ROWS];
#pragma unroll
    for (int i = 0; i < ROWS; i++) c[i] = 0.0f;

    const ulonglong2 be = *(const ulonglong2*)&g_bg_e[4 * t];
    const ulonglong2 bd = *(const ulonglong2*)&g_bg_d[4 * t];
    __syncthreads();

    // ================= encoder =================
    for (int step = 0; step < LEN; step++) {
        if (t < ROWS * ID) {
            int r = t / ID, k = t - r * ID;
            Ax[k * AST + r] = pack2(x[(size_t)(r0 + r) * (LEN * ID) + step * ID + k]);
        }
        __syncthreads();

        u64 acc[ROWS][2];
#pragma unroll
        for (int i = 0; i < ROWS; i++) { acc[i][0] = be.x; acc[i][1] = be.y; }
        gemm_acc(acc, Ax, g_Wg_e_ih, ID, t);
        gemm_acc(acc, Ah, g_Wg_e_hh, HD, t);
        __syncthreads();   // all reads of Ah done before overwrite

        float* ebase = &g_enc[(size_t)r0 * (LEN * HD) + (size_t)step * HD + t];
#pragma unroll
        for (int i = 0; i < ROWS; i++) {
            float2 f_if = unpk(acc[i][0]);
            float2 f_go = unpk(acc[i][1]);
            float cc = sigmf(f_if.y) * c[i] + sigmf(f_if.x) * tanhf(f_go.x);
            float hh = sigmf(f_go.y) * tanhf(cc);
            c[i] = cc;
            Ah[t * AST + i] = pack2(hh);
            ebase[(size_t)i * (LEN * HD)] = hh;
        }
        __syncthreads();
    }

    // ================= decoder init =================
#pragma unroll
    for (int i = 0; i < ROWS; i++) c[i] = 0.0f;
    if (t < ROWS) {
#pragma unroll
        for (int k = 0; k < OD; k++) Ain[k * AST + t] = pack2(k == 4 ? 1.0f : 0.0f);
        Ain[262 * AST + t] = 0ULL;
        Ain[263 * AST + t] = 0ULL;
    }
    __syncthreads();

    // ================= decoder =================
    for (int step = 0; step < TS; step++) {
        // ---- attention scores: s[r][l] = [h, tok] . attnT[:, l] + b[l]
        {
            int l = t & 63, rg = t >> 6;   // 4 row-groups of 8 rows
            float sc[8];
            float bias = (l < LEN) ? attn_b[l] : 0.0f;
#pragma unroll
            for (int i = 0; i < 8; i++) sc[i] = bias;
            const u64* Ar = Ah + rg * 8;
            for (int k = 0; k < HD; k++) {
                float w = __ldg(&g_attnT[k * 64 + l]);
                const u64* ak = Ar + k * AST;
#pragma unroll
                for (int i = 0; i < 8; i++) sc[i] += lo32(ak[i]) * w;
            }
#pragma unroll
            for (int k = 0; k < OD; k++) {
                float w = __ldg(&g_attnT[(HD + k) * 64 + l]);
                const u64* ak = Ain + k * AST + rg * 8;
#pragma unroll
                for (int i = 0; i < 8; i++) sc[i] += lo32(ak[i]) * w;
            }
            if (l < LEN) {
#pragma unroll
                for (int i = 0; i < 8; i++) s_s[(rg * 8 + i) * 65 + l] = sc[i];
            }
        }
        __syncthreads();
        // ---- softmax (1 thread per row)
        if (t < ROWS) {
            float* sp = &s_s[t * 65];
            float m = -1e30f;
            for (int l = 0; l < LEN; l++) m = fmaxf(m, sp[l]);
            float ss = 0.0f;
            for (int l = 0; l < LEN; l++) { float e = __expf(sp[l] - m); sp[l] = e; ss += e; }
            float inv = 1.0f / ss;
            for (int l = 0; l < LEN; l++) sp[l] *= inv;
        }
        __syncthreads();
        // ---- ctx: thread (r = t>>3, 32 h-cols) -> write dup'd into Ain rows 6..261
        {
            int r = t >> 3, c8 = t & 7;
            u64 a16[16];
#pragma unroll
            for (int j = 0; j < 16; j++) a16[j] = 0ULL;
            const float* ep = &g_enc[(size_t)(r0 + r) * (LEN * HD) + c8 * 32];
            const float* ap = &s_s[r * 65];
            for (int l = 0; l < LEN; l++) {
                u64 aw = pack2(ap[l]);
                const ulonglong2* e2 = (const ulonglong2*)(ep + (size_t)l * HD);
#pragma unroll
                for (int j = 0; j < 8; j++) {
                    ulonglong2 ev = e2[j];
                    a16[2 * j]     = fma2(aw, ev.x, a16[2 * j]);
                    a16[2 * j + 1] = fma2(aw, ev.y, a16[2 * j + 1]);
                }
            }
            int kb = 6 + c8 * 32;
#pragma unroll
            for (int j = 0; j < 16; j++) {
                float2 f = unpk(a16[j]);
                Ain[(kb + 2 * j) * AST + r]     = pack2(f.x);
                Ain[(kb + 2 * j + 1) * AST + r] = pack2(f.y);
            }
        }
        __syncthreads();

        // ---- decoder LSTM gates + cell update (c in registers, gates never in smem)
        u64 acc[ROWS][2];
#pragma unroll
        for (int i = 0; i < ROWS; i++) { acc[i][0] = bd.x; acc[i][1] = bd.y; }
        gemm_acc(acc, Ain, g_Wg_d_ih, KDD, t);
        gemm_acc(acc, Ah,  g_Wg_d_hh, HD, t);
        __syncthreads();
#pragma unroll
        for (int i = 0; i < ROWS; i++) {
            float2 f_if = unpk(acc[i][0]);
            float2 f_go = unpk(acc[i][1]);
            float cc = sigmf(f_if.y) * c[i] + sigmf(f_if.x) * tanhf(f_go.x);
            float hh = sigmf(f_go.y) * tanhf(cc);
            c[i] = cc;
            Ah[t * AST + i] = pack2(hh);
        }
        __syncthreads();

        // ---- l1: z = relu(h @ l1T + b1); thread (2 cols, 16 rows)
        {
            int c2 = t & 127, rh = t >> 7;
            u64 a16[16];
            u64 lb = *(const u64*)&l1b[2 * c2];
#pragma unroll
            for (int i = 0; i < 16; i++) a16[i] = lb;
            const float* Wp = &g_l1T[2 * c2];
            const u64* Ar = Ah + rh * 16;
            for (int k = 0; k < HD; k++) {
                u64 w = *(const u64*)(Wp + k * HD);
                const u64* ak = Ar + k * AST;
#pragma unroll
                for (int i = 0; i < 16; i++) a16[i] = fma2(ak[i], w, a16[i]);
            }
#pragma unroll
            for (int i = 0; i < 16; i++) {
                float2 f = unpk(a16[i]);
                z_s[(2 * c2) * 33 + rh * 16 + i]     = fmaxf(f.x, 0.0f);
                z_s[(2 * c2 + 1) * 33 + rh * 16 + i] = fmaxf(f.y, 0.0f);
            }
        }
        __syncthreads();

        // ---- l2 + output + token feedback
        if (t < ROWS * OD) {
            int r = t / OD, o = t - r * OD;
            float s = l2b[o];
            for (int u = 0; u < HD; u++) s += z_s[u * 33 + r] * __ldg(&g_l2T[u * OD + o]);
            out[(size_t)(r0 + r) * (TS * OD) + step * OD + o] = s;
            Ain[o * AST + r] = pack2(s);
        }
        __syncthreads();
    }
}

extern "C" void kernel_launch(void* const* d_in, const int* in_sizes, int n_in,
                              void* d_out, int out_size) {
    const float* x    = (const float*)d_in[0];
    const float* eWih = (const float*)d_in[2];
    const float* eWhh = (const float*)d_in[3];
    const float* ebih = (const float*)d_in[4];
    const float* ebhh = (const float*)d_in[5];
    const float* aW   = (const float*)d_in[6];
    const float* ab   = (const float*)d_in[7];
    const float* dWih = (const float*)d_in[8];
    const float* dWhh = (const float*)d_in[9];
    const float* dbih = (const float*)d_in[10];
    const float* dbhh = (const float*)d_in[11];
    const float* l1W  = (const float*)d_in[12];
    const float* l1b  = (const float*)d_in[13];
    const float* l2W  = (const float*)d_in[14];
    const float* l2b  = (const float*)d_in[15];
    float* out = (float*)d_out;

    prep_kernel<<<256, 256>>>(eWih, eWhh, ebih, ebhh, aW, dWih, dWhh, dbih, dbhh, l1W, l2W);

    const int smem_bytes = (HD * AST + KDD * AST + 8 * AST) * (int)sizeof(u64)
                         + (32 * 65 + 256 * 33) * (int)sizeof(float);
    cudaFuncSetAttribute(seq_kernel, cudaFuncAttributeMaxDynamicSharedMemorySize, smem_bytes);
    seq_kernel<<<NCTA, NTH, smem_bytes>>>(x, ab, l1b, l2b, out);
}

// round 4
// speedup vs baseline: 1.7271x; 1.4069x over previous
#include <cuda_runtime.h>

#define BN   4096
#define LEN  60
#define TS   60
#define HD   256
#define ID   6
#define OD   6
#define GD   1024
#define ROWS 32
#define NTH  256
#define KDD  264
#define NCTA (BN / ROWS)
#define AST  34          // float stride of activation buffers [k][row] (even -> 8B aligned pairs)

typedef unsigned long long u64;

// ---------------- device scratch (allocation-free) ----------------
// Gate-interleaved weights: Wg[k][u*4+g] = W_orig[g*256+u][k]  (g: 0=i,1=f,2=g,3=o)
__device__ __align__(16) float g_Wg_e_ih[8 * GD];      // padded to 8 k-rows (6,7 zero)
__device__ __align__(16) float g_Wg_e_hh[HD * GD];
__device__ __align__(16) float g_bg_e[GD];
__device__ __align__(16) float g_Wg_d_ih[KDD * GD];    // k rows 262..263 zero
__device__ __align__(16) float g_Wg_d_hh[HD * GD];
__device__ __align__(16) float g_bg_d[GD];
__device__ __align__(16) float g_l1T[HD * HD];         // [k][u]
__device__ __align__(16) float g_l2T[HD * OD];         // [u][o]
__device__ __align__(16) float g_attnT[262 * 60];      // [k][l]
__device__ float g_enc[(size_t)BN * LEN * HD];

// ---------------- packed fp32x2 helpers ----------------
__device__ __forceinline__ u64 pack2(float v) {
    u64 r; asm("mov.b64 %0, {%1, %1};" : "=l"(r) : "f"(v)); return r;
}
__device__ __forceinline__ u64 fma2(u64 a, u64 b, u64 c) {
    u64 d; asm("fma.rn.f32x2 %0, %1, %2, %3;" : "=l"(d) : "l"(a), "l"(b), "l"(c)); return d;
}
__device__ __forceinline__ float2 unpk(u64 v) {
    float2 f; asm("mov.b64 {%0, %1}, %2;" : "=f"(f.x), "=f"(f.y) : "l"(v)); return f;
}
__device__ __forceinline__ float sigmf(float x) { return 1.0f / (1.0f + __expf(-x)); }

__device__ __forceinline__ unsigned su32(const void* p) {
    unsigned a;
    asm("{ .reg .u64 t; cvta.to.shared.u64 t, %1; cvt.u32.u64 %0, t; }" : "=r"(a) : "l"(p));
    return a;
}
__device__ __forceinline__ void cp16(unsigned d, const void* s) {
    asm volatile("cp.async.cg.shared.global [%0], [%1], 16;" :: "r"(d), "l"(s));
}
__device__ __forceinline__ void cpcommit() { asm volatile("cp.async.commit_group;"); }
__device__ __forceinline__ void cpwait1()  { asm volatile("cp.async.wait_group 1;"); }
__device__ __forceinline__ void cpwait0()  { asm volatile("cp.async.wait_group 0;"); }

// copy one 16KB weight tile (4096 floats): thread t moves 64B
__device__ __forceinline__ void cp_tile(unsigned dst_s, const float* src, int t) {
    unsigned d = dst_s + (unsigned)(t * 64);
    const char* s = (const char*)src + t * 64;
    cp16(d, s); cp16(d + 16, s + 16); cp16(d + 32, s + 32); cp16(d + 48, s + 48);
    cpcommit();
}

// main-gemm tile: 4 k-rows; thread t owns cols 4t..4t+3 (unit t, gates i,f,g,o),
// acc[i][g] = fp32x2 over rows (2i, 2i+1)
__device__ __forceinline__ void tile4(u64 acc[16][4], const float* __restrict__ Ak,
                                      const float* __restrict__ buf, int t) {
#pragma unroll
    for (int kk = 0; kk < 4; kk++) {
        float4 w = *(const float4*)&buf[kk * GD + 4 * t];
        u64 b0 = pack2(w.x), b1 = pack2(w.y), b2 = pack2(w.z), b3 = pack2(w.w);
        const u64* ap = (const u64*)(Ak + kk * AST);
#pragma unroll
        for (int i = 0; i < 16; i++) {
            u64 av = ap[i];
            acc[i][0] = fma2(av, b0, acc[i][0]);
            acc[i][1] = fma2(av, b1, acc[i][1]);
            acc[i][2] = fma2(av, b2, acc[i][2]);
            acc[i][3] = fma2(av, b3, acc[i][3]);
        }
    }
}

// two-segment pipelined gemm (tiles of 4 k-rows x 1024 cols)
__device__ __forceinline__ void gemm_pipe(u64 acc[16][4],
        const float* W0, const float* A0, int n0,
        const float* W1, const float* A1, int n1,
        float* wbuf, unsigned wbuf_s, int t) {
    const int NT = n0 + n1;
    cp_tile(wbuf_s, W0, t);
    {
        const float* w1 = (1 < n0) ? (W0 + 4096) : (W1 + (1 - n0) * 4096);
        cp_tile(wbuf_s + 16384, w1, t);
    }
#pragma unroll 1
    for (int j = 0; j < NT; j++) {
        if (j + 1 < NT) cpwait1(); else cpwait0();
        __syncthreads();
        if (j + 2 < NT) {
            int jj = j + 2;
            const float* ws = (jj < n0) ? (W0 + jj * 4096) : (W1 + (jj - n0) * 4096);
            cp_tile(wbuf_s + (unsigned)((jj % 3) * 16384), ws, t);
        }
        const float* Ak = (j < n0) ? (A0 + j * 4 * AST) : (A1 + (j - n0) * 4 * AST);
        tile4(acc, Ak, wbuf + (j % 3) * 4096, t);
    }
}

// l1 tile: 16 k-rows x 256 cols; thread (c2 = cols 2c2,2c2+1; rh = rowpairs rh*8..rh*8+7)
__device__ __forceinline__ void tile16_l1(u64 acc[8][2], const float* __restrict__ Ak,
                                          const float* __restrict__ buf, int c2, int rh) {
#pragma unroll 4
    for (int kk = 0; kk < 16; kk++) {
        float2 w = *(const float2*)&buf[kk * 256 + 2 * c2];
        u64 b0 = pack2(w.x), b1 = pack2(w.y);
        const u64* ap = (const u64*)(Ak + kk * AST) + rh * 8;
#pragma unroll
        for (int i = 0; i < 8; i++) {
            u64 av = ap[i];
            acc[i][0] = fma2(av, b0, acc[i][0]);
            acc[i][1] = fma2(av, b1, acc[i][1]);
        }
    }
}

__device__ __forceinline__ void gemm_pipe_l1(u64 acc[8][2], const float* W0, const float* A0,
                                             float* wbuf, unsigned wbuf_s, int c2, int rh, int t) {
    const int NT = 16;
    cp_tile(wbuf_s, W0, t);
    cp_tile(wbuf_s + 16384, W0 + 4096, t);
#pragma unroll 1
    for (int j = 0; j < NT; j++) {
        if (j + 1 < NT) cpwait1(); else cpwait0();
        __syncthreads();
        if (j + 2 < NT) cp_tile(wbuf_s + (unsigned)(((j + 2) % 3) * 16384), W0 + (j + 2) * 4096, t);
        tile16_l1(acc, A0 + j * 16 * AST, wbuf + (j % 3) * 4096, c2, rh);
    }
}

// ---------------- prep ----------------
__global__ void prep_kernel(const float* __restrict__ eWih, const float* __restrict__ eWhh,
                            const float* __restrict__ ebih, const float* __restrict__ ebhh,
                            const float* __restrict__ aW,
                            const float* __restrict__ dWih, const float* __restrict__ dWhh,
                            const float* __restrict__ dbih, const float* __restrict__ dbhh,
                            const float* __restrict__ l1W, const float* __restrict__ l2W) {
    int tid = blockIdx.x * blockDim.x + threadIdx.x;
    int stride = gridDim.x * blockDim.x;
    for (int i = tid; i < 8 * GD; i += stride) {
        int k = i / GD, cc = i % GD, u = cc >> 2, g = cc & 3;
        g_Wg_e_ih[i] = (k < ID) ? eWih[(g * HD + u) * ID + k] : 0.0f;
    }
    for (int i = tid; i < HD * GD; i += stride) {
        int k = i / GD, cc = i % GD, u = cc >> 2, g = cc & 3;
        g_Wg_e_hh[i] = eWhh[(g * HD + u) * HD + k];
    }
    for (int i = tid; i < GD; i += stride) {
        int u = i >> 2, g = i & 3;
        g_bg_e[i] = ebih[g * HD + u] + ebhh[g * HD + u];
    }
    for (int i = tid; i < KDD * GD; i += stride) {
        int k = i / GD, cc = i % GD, u = cc >> 2, g = cc & 3;
        g_Wg_d_ih[i] = (k < 262) ? dWih[(g * HD + u) * 262 + k] : 0.0f;
    }
    for (int i = tid; i < HD * GD; i += stride) {
        int k = i / GD, cc = i % GD, u = cc >> 2, g = cc & 3;
        g_Wg_d_hh[i] = dWhh[(g * HD + u) * HD + k];
    }
    for (int i = tid; i < GD; i += stride) {
        int u = i >> 2, g = i & 3;
        g_bg_d[i] = dbih[g * HD + u] + dbhh[g * HD + u];
    }
    for (int i = tid; i < HD * HD; i += stride) { int k = i / HD, u = i % HD; g_l1T[i] = l1W[u * HD + k]; }
    for (int i = tid; i < HD * OD; i += stride) { int k = i / OD, o = i % OD; g_l2T[i] = l2W[o * HD + k]; }
    for (int i = tid; i < 262 * 60; i += stride) {
        int k = i / 60, l = i % 60;
        g_attnT[i] = aW[l * 262 + k];
    }
}

// ---------------- main ----------------
__global__ void __launch_bounds__(NTH, 1) seq_kernel(const float* __restrict__ x,
                                                     const float* __restrict__ attn_b,
                                                     const float* __restrict__ l1b,
                                                     const float* __restrict__ l2b,
                                                     float* __restrict__ out) {
    extern __shared__ float sm[];
    float* Ah      = sm;                    // [256*34]  h (plain f32, [k][row])
    float* Ain     = Ah + 256 * AST;        // [264*34]  dec input
    float* Ax      = Ain + 264 * AST;       // [8*34]    enc x (rows 6,7 zero)
    float* attnT_s = Ax + 8 * AST;          // [262*60]
    float* wbuf    = attnT_s + 262 * 60;    // [3*4096]  cp.async weight tiles
    float* s_s     = wbuf + 3 * 4096;       // [32*60]   scores
    float* z_s     = s_s + 32 * 60;         // [256*33]  l1 output [u][r]
    float* l2T_s   = z_s + 256 * 33;        // [256*6]

    const int t  = threadIdx.x;
    const int r0 = blockIdx.x * ROWS;
    const unsigned wbuf_s = su32(wbuf);

    for (int i = t; i < 256 * AST; i += NTH) Ah[i] = 0.0f;
    for (int i = t; i < 8 * AST; i += NTH) Ax[i] = 0.0f;
    if (t < 32) { Ain[262 * AST + t] = 0.0f; Ain[263 * AST + t] = 0.0f; }

    float c[32];
#pragma unroll
    for (int i = 0; i < 32; i++) c[i] = 0.0f;

    float4 bev = *(const float4*)&g_bg_e[4 * t];
    u64 beq0 = pack2(bev.x), beq1 = pack2(bev.y), beq2 = pack2(bev.z), beq3 = pack2(bev.w);
    float4 bdv = *(const float4*)&g_bg_d[4 * t];
    u64 bdq0 = pack2(bdv.x), bdq1 = pack2(bdv.y), bdq2 = pack2(bdv.z), bdq3 = pack2(bdv.w);
    __syncthreads();

    // ================= encoder =================
    for (int step = 0; step < LEN; step++) {
        if (t < ROWS * ID) {
            int r = t / ID, k = t - r * ID;
            Ax[k * AST + r] = x[(size_t)(r0 + r) * (LEN * ID) + step * ID + k];
        }
        // (ordered before first tile compute by the pipe's internal barrier)

        u64 acc[16][4];
#pragma unroll
        for (int i = 0; i < 16; i++) { acc[i][0] = beq0; acc[i][1] = beq1; acc[i][2] = beq2; acc[i][3] = beq3; }
        gemm_pipe(acc, g_Wg_e_ih, Ax, 2, g_Wg_e_hh, Ah, 64, wbuf, wbuf_s, t);
        __syncthreads();   // all tile computes read Ah before overwrite

        float* eb = &g_enc[(size_t)r0 * (LEN * HD) + (size_t)step * HD + t];
#pragma unroll
        for (int i = 0; i < 16; i++) {
            float2 gi = unpk(acc[i][0]), gf = unpk(acc[i][1]);
            float2 gg = unpk(acc[i][2]), go = unpk(acc[i][3]);
            float ca = sigmf(gf.x) * c[2 * i]     + sigmf(gi.x) * tanhf(gg.x);
            float cb = sigmf(gf.y) * c[2 * i + 1] + sigmf(gi.y) * tanhf(gg.y);
            float ha = sigmf(go.x) * tanhf(ca);
            float hb = sigmf(go.y) * tanhf(cb);
            c[2 * i] = ca; c[2 * i + 1] = cb;
            *(float2*)&Ah[t * AST + 2 * i] = make_float2(ha, hb);
            eb[(size_t)(2 * i) * (LEN * HD)]     = ha;
            eb[(size_t)(2 * i + 1) * (LEN * HD)] = hb;
        }
        __syncthreads();
    }

    // ================= decoder init + smem fills =================
    for (int i = t; i < 262 * 60; i += NTH) attnT_s[i] = g_attnT[i];
    for (int i = t; i < 256 * 6; i += NTH) l2T_s[i] = g_l2T[i];
#pragma unroll
    for (int i = 0; i < 32; i++) c[i] = 0.0f;
    if (t < 32) {
#pragma unroll
        for (int k = 0; k < OD; k++) Ain[k * AST + t] = (k == 4) ? 1.0f : 0.0f;
    }
    const int lA = t & 63, rgp = t >> 6;
    const u64 abq = pack2((lA < LEN) ? attn_b[lA] : 0.0f);
    const int c2v = t & 127, rhv = t >> 7;
    const u64 l1bq0 = pack2(l1b[2 * c2v]), l1bq1 = pack2(l1b[2 * c2v + 1]);
    const int rL2 = t / 6, oL2 = t - 6 * (t / 6);
    const float l2bv = (t < ROWS * OD) ? l2b[oL2] : 0.0f;
    __syncthreads();

    // ================= decoder =================
    for (int step = 0; step < TS; step++) {
        // ---- scores: s[r][l] = [h | tok] . attnT[:, l] + b[l]
        if (lA < LEN) {
            u64 sc0 = abq, sc1 = abq, sc2 = abq, sc3 = abq;
#pragma unroll 8
            for (int k = 0; k < HD; k++) {
                u64 w = pack2(attnT_s[k * 60 + lA]);
                const u64* ap = (const u64*)(Ah + k * AST) + rgp * 4;
                sc0 = fma2(ap[0], w, sc0); sc1 = fma2(ap[1], w, sc1);
                sc2 = fma2(ap[2], w, sc2); sc3 = fma2(ap[3], w, sc3);
            }
#pragma unroll
            for (int k = 0; k < OD; k++) {
                u64 w = pack2(attnT_s[(HD + k) * 60 + lA]);
                const u64* ap = (const u64*)(Ain + k * AST) + rgp * 4;
                sc0 = fma2(ap[0], w, sc0); sc1 = fma2(ap[1], w, sc1);
                sc2 = fma2(ap[2], w, sc2); sc3 = fma2(ap[3], w, sc3);
            }
            float2 f0 = unpk(sc0), f1 = unpk(sc1), f2 = unpk(sc2), f3 = unpk(sc3);
            int rb = rgp * 8;
            s_s[(rb + 0) * 60 + lA] = f0.x; s_s[(rb + 1) * 60 + lA] = f0.y;
            s_s[(rb + 2) * 60 + lA] = f1.x; s_s[(rb + 3) * 60 + lA] = f1.y;
            s_s[(rb + 4) * 60 + lA] = f2.x; s_s[(rb + 5) * 60 + lA] = f2.y;
            s_s[(rb + 6) * 60 + lA] = f3.x; s_s[(rb + 7) * 60 + lA] = f3.y;
        }
        __syncthreads();
        // ---- softmax
        if (t < ROWS) {
            float* sp = &s_s[t * 60];
            float m = -1e30f;
            for (int l = 0; l < LEN; l++) m = fmaxf(m, sp[l]);
            float ss = 0.0f;
            for (int l = 0; l < LEN; l++) { float e = __expf(sp[l] - m); sp[l] = e; ss += e; }
            float inv = 1.0f / ss;
            for (int l = 0; l < LEN; l++) sp[l] *= inv;
        }
        __syncthreads();
        // ---- ctx: thread (r = t>>3, 32 h-cols) -> Ain rows 6..261 (plain f32)
        {
            int r = t >> 3, c8 = t & 7;
            u64 a16[16];
#pragma unroll
            for (int j = 0; j < 16; j++) a16[j] = 0ULL;
            const float* ep  = &g_enc[(size_t)(r0 + r) * (LEN * HD) + c8 * 32];
            const float* apw = &s_s[r * 60];
#pragma unroll 4
            for (int l = 0; l < LEN; l++) {
                u64 aw = pack2(apw[l]);
                const ulonglong2* e2 = (const ulonglong2*)(ep + (size_t)l * HD);
#pragma unroll
                for (int j = 0; j < 8; j++) {
                    ulonglong2 ev = e2[j];
                    a16[2 * j]     = fma2(aw, ev.x, a16[2 * j]);
                    a16[2 * j + 1] = fma2(aw, ev.y, a16[2 * j + 1]);
                }
            }
            int kb = 6 + c8 * 32;
#pragma unroll
            for (int j = 0; j < 16; j++) {
                float2 f = unpk(a16[j]);
                Ain[(kb + 2 * j) * AST + r]     = f.x;
                Ain[(kb + 2 * j + 1) * AST + r] = f.y;
            }
        }
        __syncthreads();

        // ---- decoder gates (pipelined ih K=264 + hh K=256)
        u64 acc[16][4];
#pragma unroll
        for (int i = 0; i < 16; i++) { acc[i][0] = bdq0; acc[i][1] = bdq1; acc[i][2] = bdq2; acc[i][3] = bdq3; }
        gemm_pipe(acc, g_Wg_d_ih, Ain, 66, g_Wg_d_hh, Ah, 64, wbuf, wbuf_s, t);
        __syncthreads();
#pragma unroll
        for (int i = 0; i < 16; i++) {
            float2 gi = unpk(acc[i][0]), gf = unpk(acc[i][1]);
            float2 gg = unpk(acc[i][2]), go = unpk(acc[i][3]);
            float ca = sigmf(gf.x) * c[2 * i]     + sigmf(gi.x) * tanhf(gg.x);
            float cb = sigmf(gf.y) * c[2 * i + 1] + sigmf(gi.y) * tanhf(gg.y);
            float ha = sigmf(go.x) * tanhf(ca);
            float hb = sigmf(go.y) * tanhf(cb);
            c[2 * i] = ca; c[2 * i + 1] = cb;
            *(float2*)&Ah[t * AST + 2 * i] = make_float2(ha, hb);
        }
        __syncthreads();

        // ---- l1 (pipelined): z = relu(h @ l1T + b1)
        {
            u64 a8[8][2];
#pragma unroll
            for (int i = 0; i < 8; i++) { a8[i][0] = l1bq0; a8[i][1] = l1bq1; }
            gemm_pipe_l1(a8, g_l1T, Ah, wbuf, wbuf_s, c2v, rhv, t);
#pragma unroll
            for (int i = 0; i < 8; i++) {
                float2 f0 = unpk(a8[i][0]), f1 = unpk(a8[i][1]);
                int rr = rhv * 16 + 2 * i;
                z_s[(2 * c2v) * 33 + rr]     = fmaxf(f0.x, 0.0f);
                z_s[(2 * c2v) * 33 + rr + 1] = fmaxf(f0.y, 0.0f);
                z_s[(2 * c2v + 1) * 33 + rr]     = fmaxf(f1.x, 0.0f);
                z_s[(2 * c2v + 1) * 33 + rr + 1] = fmaxf(f1.y, 0.0f);
            }
        }
        __syncthreads();

        // ---- l2 + output + token feedback
        if (t < ROWS * OD) {
            float s = l2bv;
#pragma unroll 8
            for (int u = 0; u < HD; u++) s += z_s[u * 33 + rL2] * l2T_s[u * 6 + oL2];
            out[(size_t)(r0 + rL2) * (TS * OD) + step * OD + oL2] = s;
            Ain[oL2 * AST + rL2] = s;
        }
        __syncthreads();
    }
}

extern "C" void kernel_launch(void* const* d_in, const int* in_sizes, int n_in,
                              void* d_out, int out_size) {
    const float* x    = (const float*)d_in[0];
    const float* eWih = (const float*)d_in[2];
    const float* eWhh = (const float*)d_in[3];
    const float* ebih = (const float*)d_in[4];
    const float* ebhh = (const float*)d_in[5];
    const float* aW   = (const float*)d_in[6];
    const float* ab   = (const float*)d_in[7];
    const float* dWih = (const float*)d_in[8];
    const float* dWhh = (const float*)d_in[9];
    const float* dbih = (const float*)d_in[10];
    const float* dbhh = (const float*)d_in[11];
    const float* l1W  = (const float*)d_in[12];
    const float* l1b  = (const float*)d_in[13];
    const float* l2W  = (const float*)d_in[14];
    const float* l2b  = (const float*)d_in[15];
    float* out = (float*)d_out;

    prep_kernel<<<256, 256>>>(eWih, eWhh, ebih, ebhh, aW, dWih, dWhh, dbih, dbhh, l1W, l2W);

    const int smem_floats = 256 * AST + 264 * AST + 8 * AST + 262 * 60 + 3 * 4096
                          + 32 * 60 + 256 * 33 + 256 * 6;
    const int smem_bytes = smem_floats * (int)sizeof(float);   // 231,456 B
    cudaFuncSetAttribute(seq_kernel, cudaFuncAttributeMaxDynamicSharedMemorySize, smem_bytes);
    seq_kernel<<<NCTA, NTH, smem_bytes>>>(x, ab, l1b, l2b, out);
}

// round 5
// speedup vs baseline: 1.8548x; 1.0739x over previous
#include <cuda_runtime.h>

#define BN   4096
#define LEN  60
#define TS   60
#define HD   256
#define ID   6
#define OD   6
#define GD   1024
#define ROWS 32
#define NTH  512
#define KDD  264
#define NCTA (BN / ROWS)
#define AST  34          // float stride of activation buffers [k][row]

typedef unsigned long long u64;

// ---------------- device scratch (allocation-free) ----------------
// Gate-interleaved weights: Wg[k][u*4+g] = W_orig[g*256+u][k]  (g: 0=i,1=f,2=g,3=o)
__device__ __align__(16) float g_Wg_e_ih[8 * GD];      // padded to 8 k-rows (6,7 zero)
__device__ __align__(16) float g_Wg_e_hh[HD * GD];
__device__ __align__(16) float g_bg_e[GD];
__device__ __align__(16) float g_Wg_d_ih[KDD * GD];    // k rows 262..263 zero
__device__ __align__(16) float g_Wg_d_hh[HD * GD];
__device__ __align__(16) float g_bg_d[GD];
__device__ __align__(16) float g_l1T[HD * HD];         // [k][u]
__device__ __align__(16) float g_l2T[HD * OD];         // [u][o]
__device__ __align__(16) float g_attnT[262 * 60];      // [k][l]
__device__ float g_enc[(size_t)BN * LEN * HD];

// ---------------- packed fp32x2 helpers ----------------
__device__ __forceinline__ u64 pack2(float v) {
    u64 r; asm("mov.b64 %0, {%1, %1};" : "=l"(r) : "f"(v)); return r;
}
__device__ __forceinline__ u64 fma2(u64 a, u64 b, u64 c) {
    u64 d; asm("fma.rn.f32x2 %0, %1, %2, %3;" : "=l"(d) : "l"(a), "l"(b), "l"(c)); return d;
}
__device__ __forceinline__ float2 unpk(u64 v) {
    float2 f; asm("mov.b64 {%0, %1}, %2;" : "=f"(f.x), "=f"(f.y) : "l"(v)); return f;
}
__device__ __forceinline__ float sigmf(float x) { return 1.0f / (1.0f + __expf(-x)); }

__device__ __forceinline__ unsigned su32(const void* p) {
    unsigned a;
    asm("{ .reg .u64 t; cvta.to.shared.u64 t, %1; cvt.u32.u64 %0, t; }" : "=r"(a) : "l"(p));
    return a;
}
__device__ __forceinline__ void cp16(unsigned d, const void* s) {
    asm volatile("cp.async.cg.shared.global [%0], [%1], 16;" :: "r"(d), "l"(s));
}
__device__ __forceinline__ void cpcommit() { asm volatile("cp.async.commit_group;"); }
__device__ __forceinline__ void cpwait1()  { asm volatile("cp.async.wait_group 1;"); }
__device__ __forceinline__ void cpwait0()  { asm volatile("cp.async.wait_group 0;"); }

// copy one 32KB tile (8192 floats): each of 512 threads moves 64B
__device__ __forceinline__ void cp_tile(unsigned dst_s, const float* src, int t) {
    unsigned d = dst_s + (unsigned)(t * 64);
    const char* s = (const char*)src + t * 64;
    cp16(d, s); cp16(d + 16, s + 16); cp16(d + 32, s + 32); cp16(d + 48, s + 48);
    cpcommit();
}

// main-gemm tile: 8 k-rows; thread owns unit u (cols 4u..4u+3), rows half*16..half*16+15.
// acc[i][g] = fp32x2 over row pair (half*16+2i, +1)
__device__ __forceinline__ void tile8(u64 acc[8][4], const float* __restrict__ Ak,
                                      const float* __restrict__ buf, int u, int half) {
#pragma unroll
    for (int kk = 0; kk < 8; kk++) {
        float4 w = *(const float4*)&buf[kk * GD + 4 * u];
        u64 b0 = pack2(w.x), b1 = pack2(w.y), b2 = pack2(w.z), b3 = pack2(w.w);
        const u64* ap = (const u64*)(Ak + kk * AST) + half * 8;
#pragma unroll
        for (int i = 0; i < 8; i++) {
            u64 av = ap[i];
            acc[i][0] = fma2(av, b0, acc[i][0]);
            acc[i][1] = fma2(av, b1, acc[i][1]);
            acc[i][2] = fma2(av, b2, acc[i][2]);
            acc[i][3] = fma2(av, b3, acc[i][3]);
        }
    }
}

// two-segment pipelined gemm (tiles of 8 k-rows x 1024 cols, triple-buffered)
__device__ __forceinline__ void gemm_pipe(u64 acc[8][4],
        const float* W0, const float* A0, int n0,
        const float* W1, const float* A1, int n1,
        float* wbuf, unsigned wbuf_s, int t, int u, int half) {
    const int NT = n0 + n1;
    cp_tile(wbuf_s, W0, t);
    {
        const float* w1 = (1 < n0) ? (W0 + 8192) : (W1 + (1 - n0) * 8192);
        cp_tile(wbuf_s + 32768, w1, t);
    }
#pragma unroll 1
    for (int j = 0; j < NT; j++) {
        if (j + 1 < NT) cpwait1(); else cpwait0();
        __syncthreads();
        if (j + 2 < NT) {
            int jj = j + 2;
            const float* ws = (jj < n0) ? (W0 + jj * 8192) : (W1 + (jj - n0) * 8192);
            cp_tile(wbuf_s + (unsigned)((jj % 3) * 32768), ws, t);
        }
        const float* Ak = (j < n0) ? (A0 + j * 8 * AST) : (A1 + (j - n0) * 8 * AST);
        tile8(acc, Ak, wbuf + (j % 3) * 8192, u, half);
    }
}

// l1 tile: 32 k-rows x 256 cols; thread (c2 = cols 2c2,2c2+1; rh -> rows rh*8..rh*8+7)
__device__ __forceinline__ void tile32_l1(u64 acc[4][2], const float* __restrict__ Ak,
                                          const float* __restrict__ buf, int c2, int rh) {
#pragma unroll 8
    for (int kk = 0; kk < 32; kk++) {
        float2 w = *(const float2*)&buf[kk * 256 + 2 * c2];
        u64 b0 = pack2(w.x), b1 = pack2(w.y);
        const u64* ap = (const u64*)(Ak + kk * AST) + rh * 4;
#pragma unroll
        for (int i = 0; i < 4; i++) {
            u64 av = ap[i];
            acc[i][0] = fma2(av, b0, acc[i][0]);
            acc[i][1] = fma2(av, b1, acc[i][1]);
        }
    }
}

__device__ __forceinline__ void gemm_pipe_l1(u64 acc[4][2], const float* W0, const float* A0,
                                             float* wbuf, unsigned wbuf_s, int c2, int rh, int t) {
    const int NT = 8;
    cp_tile(wbuf_s, W0, t);
    cp_tile(wbuf_s + 32768, W0 + 8192, t);
#pragma unroll 1
    for (int j = 0; j < NT; j++) {
        if (j + 1 < NT) cpwait1(); else cpwait0();
        __syncthreads();
        if (j + 2 < NT) cp_tile(wbuf_s + (unsigned)(((j + 2) % 3) * 32768), W0 + (j + 2) * 8192, t);
        tile32_l1(acc, A0 + j * 32 * AST, wbuf + (j % 3) * 8192, c2, rh);
    }
}

// ---------------- prep ----------------
__global__ void prep_kernel(const float* __restrict__ eWih, const float* __restrict__ eWhh,
                            const float* __restrict__ ebih, const float* __restrict__ ebhh,
                            const float* __restrict__ aW,
                            const float* __restrict__ dWih, const float* __restrict__ dWhh,
                            const float* __restrict__ dbih, const float* __restrict__ dbhh,
                            const float* __restrict__ l1W, const float* __restrict__ l2W) {
    int tid = blockIdx.x * blockDim.x + threadIdx.x;
    int stride = gridDim.x * blockDim.x;
    for (int i = tid; i < 8 * GD; i += stride) {
        int k = i / GD, cc = i % GD, u = cc >> 2, g = cc & 3;
        g_Wg_e_ih[i] = (k < ID) ? eWih[(g * HD + u) * ID + k] : 0.0f;
    }
    for (int i = tid; i < HD * GD; i += stride) {
        int k = i / GD, cc = i % GD, u = cc >> 2, g = cc & 3;
        g_Wg_e_hh[i] = eWhh[(g * HD + u) * HD + k];
    }
    for (int i = tid; i < GD; i += stride) {
        int u = i >> 2, g = i & 3;
        g_bg_e[i] = ebih[g * HD + u] + ebhh[g * HD + u];
    }
    for (int i = tid; i < KDD * GD; i += stride) {
        int k = i / GD, cc = i % GD, u = cc >> 2, g = cc & 3;
        g_Wg_d_ih[i] = (k < 262) ? dWih[(g * HD + u) * 262 + k] : 0.0f;
    }
    for (int i = tid; i < HD * GD; i += stride) {
        int k = i / GD, cc = i % GD, u = cc >> 2, g = cc & 3;
        g_Wg_d_hh[i] = dWhh[(g * HD + u) * HD + k];
    }
    for (int i = tid; i < GD; i += stride) {
        int u = i >> 2, g = i & 3;
        g_bg_d[i] = dbih[g * HD + u] + dbhh[g * HD + u];
    }
    for (int i = tid; i < HD * HD; i += stride) { int k = i / HD, u = i % HD; g_l1T[i] = l1W[u * HD + k]; }
    for (int i = tid; i < HD * OD; i += stride) { int k = i / OD, o = i % OD; g_l2T[i] = l2W[o * HD + k]; }
    for (int i = tid; i < 262 * 60; i += stride) {
        int k = i / 60, l = i % 60;
        g_attnT[i] = aW[l * 262 + k];
    }
}

// ---------------- main: one CTA owns 32 batch rows end-to-end ----------------
__global__ void __launch_bounds__(NTH, 1) seq_kernel(const float* __restrict__ x,
                                                     const float* __restrict__ attn_b,
                                                     const float* __restrict__ l1b,
                                                     const float* __restrict__ l2b,
                                                     float* __restrict__ out) {
    extern __shared__ float sm[];
    float* Ah    = sm;                    // [256*34]  h (plain f32, [k][row])
    float* Ain   = Ah + 256 * AST;        // [264*34]  dec input
    float* Ax    = Ain + 264 * AST;       // [8*34]    enc x (rows 6,7 zero)
    float* wbuf  = Ax + 8 * AST;          // [3*8192]  cp.async weight tiles
    float* s_s   = wbuf + 3 * 8192;       // [32*60]   scores
    float* z_s   = s_s + 32 * 60;         // [256*33]  l1 output [u][r]
    float* l2T_s = z_s + 256 * 33;        // [256*6]
    float* be_s  = l2T_s + 256 * 6;       // [1024]
    float* bd_s  = be_s + GD;             // [1024]

    const int t    = threadIdx.x;
    const int r0   = blockIdx.x * ROWS;
    const int u    = t & 255;             // unit (gate cols 4u..4u+3)
    const int half = t >> 8;              // row half: rows half*16 .. half*16+15
    const unsigned wbuf_s = su32(wbuf);

    for (int i = t; i < 256 * AST; i += NTH) Ah[i] = 0.0f;
    for (int i = t; i < 8 * AST; i += NTH) Ax[i] = 0.0f;
    for (int i = t; i < GD; i += NTH) { be_s[i] = g_bg_e[i]; bd_s[i] = g_bg_d[i]; }
    if (t < 32) { Ain[262 * AST + t] = 0.0f; Ain[263 * AST + t] = 0.0f; }

    float c[16];
#pragma unroll
    for (int i = 0; i < 16; i++) c[i] = 0.0f;
    __syncthreads();

    // ================= encoder =================
    for (int step = 0; step < LEN; step++) {
        if (t < ROWS * ID) {
            int r = t / ID, k = t - r * ID;
            Ax[k * AST + r] = x[(size_t)(r0 + r) * (LEN * ID) + step * ID + k];
        }
        u64 acc[8][4];
        {
            float4 bv = *(const float4*)&be_s[4 * u];
            u64 q0 = pack2(bv.x), q1 = pack2(bv.y), q2 = pack2(bv.z), q3 = pack2(bv.w);
#pragma unroll
            for (int i = 0; i < 8; i++) { acc[i][0] = q0; acc[i][1] = q1; acc[i][2] = q2; acc[i][3] = q3; }
        }
        gemm_pipe(acc, g_Wg_e_ih, Ax, 1, g_Wg_e_hh, Ah, 32, wbuf, wbuf_s, t, u, half);
        __syncthreads();   // all tile computes read Ah before overwrite

        float* eb = &g_enc[(size_t)r0 * (LEN * HD) + (size_t)step * HD + u];
#pragma unroll
        for (int i = 0; i < 8; i++) {
            float2 gi = unpk(acc[i][0]), gf = unpk(acc[i][1]);
            float2 gg = unpk(acc[i][2]), go = unpk(acc[i][3]);
            float ca = sigmf(gf.x) * c[2 * i]     + sigmf(gi.x) * tanhf(gg.x);
            float cb = sigmf(gf.y) * c[2 * i + 1] + sigmf(gi.y) * tanhf(gg.y);
            float ha = sigmf(go.x) * tanhf(ca);
            float hb = sigmf(go.y) * tanhf(cb);
            c[2 * i] = ca; c[2 * i + 1] = cb;
            int rr = half * 16 + 2 * i;
            *(float2*)&Ah[u * AST + rr] = make_float2(ha, hb);
            eb[(size_t)rr * (LEN * HD)]       = ha;
            eb[(size_t)(rr + 1) * (LEN * HD)] = hb;
        }
        __syncthreads();
    }

    // ================= decoder init =================
#pragma unroll
    for (int i = 0; i < 16; i++) c[i] = 0.0f;
    for (int i = t; i < 256 * 6; i += NTH) l2T_s[i] = g_l2T[i];
    if (t < 32) {
#pragma unroll
        for (int k = 0; k < OD; k++) Ain[k * AST + t] = (k == 4) ? 1.0f : 0.0f;
    }
    const int lA = t & 63, rgp = t >> 6;   // scores: 8 groups of 4 rows
    const u64 abq = pack2((lA < LEN) ? attn_b[lA] : 0.0f);
    const int c2v = t & 127, rhv = t >> 7; // l1: 2 cols, 4 row-pair groups
    const u64 l1bq0 = pack2(l1b[2 * c2v]), l1bq1 = pack2(l1b[2 * c2v + 1]);
    const int rL2 = t / 6, oL2 = t - 6 * (t / 6);
    const float l2bv = (t < ROWS * OD) ? l2b[oL2] : 0.0f;
    __syncthreads();

    // ================= decoder =================
    for (int step = 0; step < TS; step++) {
        // ---- scores: s[r][l] = [h | tok] . attnT[:, l] + b[l]  (attnT from L2)
        if (lA < LEN) {
            u64 sc0 = abq, sc1 = abq;
#pragma unroll 8
            for (int k = 0; k < HD; k++) {
                u64 w = pack2(__ldg(&g_attnT[k * 60 + lA]));
                const u64* ap = (const u64*)(Ah + k * AST) + rgp * 2;
                sc0 = fma2(ap[0], w, sc0); sc1 = fma2(ap[1], w, sc1);
            }
#pragma unroll
            for (int k = 0; k < OD; k++) {
                u64 w = pack2(__ldg(&g_attnT[(HD + k) * 60 + lA]));
                const u64* ap = (const u64*)(Ain + k * AST) + rgp * 2;
                sc0 = fma2(ap[0], w, sc0); sc1 = fma2(ap[1], w, sc1);
            }
            float2 f0 = unpk(sc0), f1 = unpk(sc1);
            int rb = rgp * 4;
            s_s[(rb + 0) * 60 + lA] = f0.x; s_s[(rb + 1) * 60 + lA] = f0.y;
            s_s[(rb + 2) * 60 + lA] = f1.x; s_s[(rb + 3) * 60 + lA] = f1.y;
        }
        __syncthreads();
        // ---- softmax: warp w handles rows 2w, 2w+1 (lane i: elems i, i+32)
        {
            int w = t >> 5, lane = t & 31;
#pragma unroll
            for (int rr = 2 * w; rr < 2 * w + 2; rr++) {
                float* sp = &s_s[rr * 60];
                float v0 = sp[lane];
                float v1 = (lane + 32 < LEN) ? sp[lane + 32] : -1e30f;
                float m = fmaxf(v0, v1);
#pragma unroll
                for (int d = 16; d > 0; d >>= 1) m = fmaxf(m, __shfl_xor_sync(~0u, m, d));
                float e0 = __expf(v0 - m);
                float e1 = (lane + 32 < LEN) ? __expf(v1 - m) : 0.0f;
                float ss = e0 + e1;
#pragma unroll
                for (int d = 16; d > 0; d >>= 1) ss += __shfl_xor_sync(~0u, ss, d);
                float inv = 1.0f / ss;
                sp[lane] = e0 * inv;
                if (lane + 32 < LEN) sp[lane + 32] = e1 * inv;
            }
        }
        __syncthreads();
        // ---- ctx: thread (r = t>>4, 16 h-cols) -> Ain rows 6..261
        {
            int r = t >> 4, c16 = t & 15;
            u64 a8[8];
#pragma unroll
            for (int j = 0; j < 8; j++) a8[j] = 0ULL;
            const float* ep  = &g_enc[(size_t)(r0 + r) * (LEN * HD) + c16 * 16];
            const float* apw = &s_s[r * 60];
#pragma unroll 4
            for (int l = 0; l < LEN; l++) {
                u64 aw = pack2(apw[l]);
                const ulonglong2* e2 = (const ulonglong2*)(ep + (size_t)l * HD);
#pragma unroll
                for (int j = 0; j < 4; j++) {
                    ulonglong2 ev = e2[j];
                    a8[2 * j]     = fma2(aw, ev.x, a8[2 * j]);
                    a8[2 * j + 1] = fma2(aw, ev.y, a8[2 * j + 1]);
                }
            }
            int kb = 6 + c16 * 16;
#pragma unroll
            for (int j = 0; j < 8; j++) {
                float2 f = unpk(a8[j]);
                Ain[(kb + 2 * j) * AST + r]     = f.x;
                Ain[(kb + 2 * j + 1) * AST + r] = f.y;
            }
        }
        __syncthreads();

        // ---- decoder gates (pipelined ih K=264 + hh K=256)
        u64 acc[8][4];
        {
            float4 bv = *(const float4*)&bd_s[4 * u];
            u64 q0 = pack2(bv.x), q1 = pack2(bv.y), q2 = pack2(bv.z), q3 = pack2(bv.w);
#pragma unroll
            for (int i = 0; i < 8; i++) { acc[i][0] = q0; acc[i][1] = q1; acc[i][2] = q2; acc[i][3] = q3; }
        }
        gemm_pipe(acc, g_Wg_d_ih, Ain, 33, g_Wg_d_hh, Ah, 32, wbuf, wbuf_s, t, u, half);
        __syncthreads();
#pragma unroll
        for (int i = 0; i < 8; i++) {
            float2 gi = unpk(acc[i][0]), gf = unpk(acc[i][1]);
            float2 gg = unpk(acc[i][2]), go = unpk(acc[i][3]);
            float ca = sigmf(gf.x) * c[2 * i]     + sigmf(gi.x) * tanhf(gg.x);
            float cb = sigmf(gf.y) * c[2 * i + 1] + sigmf(gi.y) * tanhf(gg.y);
            float ha = sigmf(go.x) * tanhf(ca);
            float hb = sigmf(go.y) * tanhf(cb);
            c[2 * i] = ca; c[2 * i + 1] = cb;
            *(float2*)&Ah[u * AST + half * 16 + 2 * i] = make_float2(ha, hb);
        }
        __syncthreads();

        // ---- l1 (pipelined): z = relu(h @ l1T + b1)
        {
            u64 a4[4][2];
#pragma unroll
            for (int i = 0; i < 4; i++) { a4[i][0] = l1bq0; a4[i][1] = l1bq1; }
            gemm_pipe_l1(a4, g_l1T, Ah, wbuf, wbuf_s, c2v, rhv, t);
#pragma unroll
            for (int i = 0; i < 4; i++) {
                float2 f0 = unpk(a4[i][0]), f1 = unpk(a4[i][1]);
                int rr = rhv * 8 + 2 * i;
                z_s[(2 * c2v) * 33 + rr]     = fmaxf(f0.x, 0.0f);
                z_s[(2 * c2v) * 33 + rr + 1] = fmaxf(f0.y, 0.0f);
                z_s[(2 * c2v + 1) * 33 + rr]     = fmaxf(f1.x, 0.0f);
                z_s[(2 * c2v + 1) * 33 + rr + 1] = fmaxf(f1.y, 0.0f);
            }
        }
        __syncthreads();

        // ---- l2 + output + token feedback
        if (t < ROWS * OD) {
            float s = l2bv;
#pragma unroll 8
            for (int uu = 0; uu < HD; uu++) s += z_s[uu * 33 + rL2] * l2T_s[uu * 6 + oL2];
            out[(size_t)(r0 + rL2) * (TS * OD) + step * OD + oL2] = s;
            Ain[oL2 * AST + rL2] = s;
        }
        __syncthreads();
    }
}

extern "C" void kernel_launch(void* const* d_in, const int* in_sizes, int n_in,
                              void* d_out, int out_size) {
    const float* x    = (const float*)d_in[0];
    const float* eWih = (const float*)d_in[2];
    const float* eWhh = (const float*)d_in[3];
    const float* ebih = (const float*)d_in[4];
    const float* ebhh = (const float*)d_in[5];
    const float* aW   = (const float*)d_in[6];
    const float* ab   = (const float*)d_in[7];
    const float* dWih = (const float*)d_in[8];
    const float* dWhh = (const float*)d_in[9];
    const float* dbih = (const float*)d_in[10];
    const float* dbhh = (const float*)d_in[11];
    const float* l1W  = (const float*)d_in[12];
    const float* l1b  = (const float*)d_in[13];
    const float* l2W  = (const float*)d_in[14];
    const float* l2b  = (const float*)d_in[15];
    float* out = (float*)d_out;

    prep_kernel<<<256, 256>>>(eWih, eWhh, ebih, ebhh, aW, dWih, dWhh, dbih, dbhh, l1W, l2W);

    const int smem_floats = 256 * AST + 264 * AST + 8 * AST + 3 * 8192
                          + 32 * 60 + 256 * 33 + 256 * 6 + 2 * GD;
    const int smem_bytes = smem_floats * (int)sizeof(float);
    cudaFuncSetAttribute(seq_kernel, cudaFuncAttributeMaxDynamicSharedMemorySize, smem_bytes);
    seq_kernel<<<NCTA, NTH, smem_bytes>>>(x, ab, l1b, l2b, out);
}